// round 3
// baseline (speedup 1.0000x reference)
#include <cuda_runtime.h>
#include <cstdint>

#define CODEBOOK 32768
#define NTOK     9216      // 1*4*48*48 tokens
#define CH_STRIDE 2304     // 48*48
#define T_STRIDE  9216     // 4 channels * 2304

#define TPB    256
#define CHUNKS 32
#define CHUNK  (CODEBOOK / CHUNKS)          // 1024 codes per chunk
#define TOKBLKS (NTOK / (TPB * 2))          // 18 token blocks (2 tokens/thread)

// Scratch (static __device__ — no allocation)
__device__ ulonglong2          g_pkA[CODEBOOK];   // (e0,e0) (e1,e1) packed f32x2
__device__ ulonglong2          g_pkB[CODEBOOK];   // (e2,e2) (e3,e3)
__device__ unsigned long long  g_pkC[CODEBOOK];   // (e2sum, e2sum)
__device__ unsigned long long  g_best[NTOK];      // lexicographic (s_bits, idx) keys

// ---------- packed f32x2 helpers ----------
static __device__ __forceinline__ unsigned long long pack2(float lo, float hi) {
    unsigned long long r;
    asm("mov.b64 %0,{%1,%2};" : "=l"(r) : "f"(lo), "f"(hi));
    return r;
}
static __device__ __forceinline__ unsigned long long mul2(unsigned long long a, unsigned long long b) {
    unsigned long long d;
    asm("mul.rn.f32x2 %0,%1,%2;" : "=l"(d) : "l"(a), "l"(b));
    return d;
}
static __device__ __forceinline__ unsigned long long add2(unsigned long long a, unsigned long long b) {
    unsigned long long d;
    asm("add.rn.f32x2 %0,%1,%2;" : "=l"(d) : "l"(a), "l"(b));
    return d;
}
// s = fma(a, b, c) per half; result returned as two scalar floats (register halves)
static __device__ __forceinline__ void fma2_unpack(unsigned long long a, unsigned long long b,
                                                   unsigned long long c, float& lo, float& hi) {
    asm("{\n\t"
        ".reg .b64 t;\n\t"
        "fma.rn.f32x2 t,%2,%3,%4;\n\t"
        "mov.b64 {%0,%1},t;\n\t"
        "}" : "=f"(lo), "=f"(hi) : "l"(a), "l"(b), "l"(c));
}

// total-order map for float bits (all scores here are positive/finite; monotonic as u32)
static __device__ __forceinline__ unsigned int ford(float v) {
    unsigned int b = __float_as_uint(v);
    return (b & 0x80000000u) ? ~b : (b | 0x80000000u);
}
static __device__ __forceinline__ unsigned long long make_key(float s, int idx) {
    return (((unsigned long long)ford(s)) << 32) | (unsigned int)idx;
}

// ---------- kernel 1: codebook transform + scratch init ----------
__global__ void vq_prep(const float4* __restrict__ emb) {
    int k = blockIdx.x * blockDim.x + threadIdx.x;
    if (k < NTOK) g_best[k] = ~0ull;
    if (k < CODEBOOK) {
        float4 e = __ldg(&emb[k]);
        // e2 = ((e0*e0 + e1*e1) + e2*e2) + e3*e3, separate rn mul/add (match jnp.sum(e*e))
        float e2 = __fadd_rn(
                     __fadd_rn(
                       __fadd_rn(__fmul_rn(e.x, e.x), __fmul_rn(e.y, e.y)),
                       __fmul_rn(e.z, e.z)),
                     __fmul_rn(e.w, e.w));
        g_pkA[k] = make_ulonglong2(pack2(e.x, e.x), pack2(e.y, e.y));
        g_pkB[k] = make_ulonglong2(pack2(e.z, e.z), pack2(e.w, e.w));
        g_pkC[k] = pack2(e2, e2);
    }
}

// ---------- kernel 2: main scan ----------
// blockIdx.x : token group (512 tokens), blockIdx.y : codebook chunk (1024 codes)
__global__ void __launch_bounds__(TPB) vq_main(const float* __restrict__ hs) {
    const int n0 = (blockIdx.x * TPB + threadIdx.x) * 2;
    const int n1 = n0 + 1;
    const int base = blockIdx.y * CHUNK;

    // Load x for both tokens: token n -> (t = n/2304, hw = n%2304), channel stride 2304
    float xa[4], xb[4];
    {
        int ta = n0 / CH_STRIDE, ha = n0 % CH_STRIDE;
        const float* pa = hs + ta * T_STRIDE + ha;
        int tb = n1 / CH_STRIDE, hb = n1 % CH_STRIDE;
        const float* pb = hs + tb * T_STRIDE + hb;
#pragma unroll
        for (int c = 0; c < 4; c++) {
            xa[c] = __ldg(pa + c * CH_STRIDE);
            xb[c] = __ldg(pb + c * CH_STRIDE);
        }
    }
    // x2 = ((x0*x0 + x1*x1) + x2*x2) + x3*x3 left-assoc, separate rn ops
    float x2a = __fadd_rn(__fadd_rn(__fadd_rn(__fmul_rn(xa[0], xa[0]), __fmul_rn(xa[1], xa[1])),
                                    __fmul_rn(xa[2], xa[2])), __fmul_rn(xa[3], xa[3]));
    float x2b = __fadd_rn(__fadd_rn(__fadd_rn(__fmul_rn(xb[0], xb[0]), __fmul_rn(xb[1], xb[1])),
                                    __fmul_rn(xb[2], xb[2])), __fmul_rn(xb[3], xb[3]));

    const unsigned long long X0 = pack2(xa[0], xb[0]);
    const unsigned long long X1 = pack2(xa[1], xb[1]);
    const unsigned long long X2 = pack2(xa[2], xb[2]);
    const unsigned long long X3 = pack2(xa[3], xb[3]);
    const unsigned long long XS = pack2(x2a, x2b);
    const unsigned long long N2 = pack2(-2.0f, -2.0f);

    float bestA = __int_as_float(0x7f800000);  // +inf
    float bestB = __int_as_float(0x7f800000);
    int biA = base, biB = base;

#pragma unroll 4
    for (int i = 0; i < CHUNK; i++) {
        const int k = base + i;
        const ulonglong2 A = g_pkA[k];
        const ulonglong2 B = g_pkB[k];
        const unsigned long long C = g_pkC[k];

        // dot = ((x0*e0 + x1*e1) + x2*e2) + x3*e3  (per-half rn, matches left-assoc mul/add)
        unsigned long long d = add2(mul2(X0, A.x), mul2(X1, A.y));
        d = add2(d, mul2(X2, B.x));
        d = add2(d, mul2(X3, B.y));
        // t = fl(x2 + e2)
        const unsigned long long T = add2(XS, C);
        // s = round(t - 2*dot)  == fl(t - fl(2*dot)) since 2*dot is exact
        float sA, sB;
        fma2_unpack(N2, d, T, sA, sB);

        if (sA < bestA) { bestA = sA; biA = k; }   // ascending k: strict < keeps first index
        if (sB < bestB) { bestB = sB; biB = k; }
    }

    atomicMin(&g_best[n0], make_key(bestA, biA));
    atomicMin(&g_best[n1], make_key(bestB, biB));
}

// ---------- kernel 3: extract indices (write as FLOAT — output buffer is fp32) ----------
__global__ void vq_final(float* __restrict__ out) {
    int n = blockIdx.x * blockDim.x + threadIdx.x;
    if (n < NTOK) {
        out[n] = (float)(unsigned int)(g_best[n] & 0xFFFFFFFFull);
    }
}

extern "C" void kernel_launch(void* const* d_in, const int* in_sizes, int n_in,
                              void* d_out, int out_size) {
    // Resolve input order robustly by element count:
    //   hidden_state: 1*4*4*48*48 = 36864 elements
    //   embedding:    32768*4     = 131072 elements
    const float*  hs;
    const float4* emb;
    if (in_sizes[0] == NTOK * 4) {
        hs  = (const float*)d_in[0];
        emb = (const float4*)d_in[1];
    } else {
        emb = (const float4*)d_in[0];
        hs  = (const float*)d_in[1];
    }
    float* out = (float*)d_out;

    vq_prep<<<CODEBOOK / 256, 256>>>(emb);
    vq_main<<<dim3(TOKBLKS, CHUNKS, 1), TPB>>>(hs);
    vq_final<<<(NTOK + 255) / 256, 256>>>(out);
}

// round 4
// speedup vs baseline: 1.3567x; 1.3567x over previous
#include <cuda_runtime.h>
#include <cstdint>

#define CODEBOOK 32768
#define NTOK     9216      // 1*4*48*48 tokens
#define CH_STRIDE 2304     // 48*48
#define T_STRIDE  9216     // 4 channels * 2304

#define TPB     128
#define TPT     4                           // tokens per thread (2 f32x2 pairs)
#define CHUNKS  32
#define CHUNK   (CODEBOOK / CHUNKS)         // 1024 codes per chunk
#define GROUP   16
#define NGROUP  (CHUNK / GROUP)             // 64 groups per chunk
#define TOKBLKS (NTOK / (TPB * TPT))        // 18 token blocks

// Scratch (static __device__ — no allocation)
__device__ ulonglong2          g_pkA[CODEBOOK];   // (e0,e0) (e1,e1) packed f32x2
__device__ ulonglong2          g_pkB[CODEBOOK];   // (e2,e2) (e3,e3)
__device__ unsigned long long  g_pkC[CODEBOOK];   // (e2sum, e2sum)
__device__ unsigned long long  g_best[NTOK];      // lexicographic (s_bits, idx) keys

// ---------- packed f32x2 helpers ----------
static __device__ __forceinline__ unsigned long long pack2(float lo, float hi) {
    unsigned long long r;
    asm("mov.b64 %0,{%1,%2};" : "=l"(r) : "f"(lo), "f"(hi));
    return r;
}
static __device__ __forceinline__ unsigned long long mul2(unsigned long long a, unsigned long long b) {
    unsigned long long d;
    asm("mul.rn.f32x2 %0,%1,%2;" : "=l"(d) : "l"(a), "l"(b));
    return d;
}
static __device__ __forceinline__ unsigned long long add2(unsigned long long a, unsigned long long b) {
    unsigned long long d;
    asm("add.rn.f32x2 %0,%1,%2;" : "=l"(d) : "l"(a), "l"(b));
    return d;
}
// s = fma(a, b, c) per half; result returned as two scalar floats (register halves)
static __device__ __forceinline__ void fma2_unpack(unsigned long long a, unsigned long long b,
                                                   unsigned long long c, float& lo, float& hi) {
    asm("{\n\t"
        ".reg .b64 t;\n\t"
        "fma.rn.f32x2 t,%2,%3,%4;\n\t"
        "mov.b64 {%0,%1},t;\n\t"
        "}" : "=f"(lo), "=f"(hi) : "l"(a), "l"(b), "l"(c));
}

// total-order map for float bits (monotonic as u32; scores here are positive)
static __device__ __forceinline__ unsigned int ford(float v) {
    unsigned int b = __float_as_uint(v);
    return (b & 0x80000000u) ? ~b : (b | 0x80000000u);
}
static __device__ __forceinline__ unsigned long long make_key(float s, int idx) {
    return (((unsigned long long)ford(s)) << 32) | (unsigned int)idx;
}

// ---------- kernel 1: codebook transform + scratch init ----------
__global__ void vq_prep(const float4* __restrict__ emb) {
    int k = blockIdx.x * blockDim.x + threadIdx.x;
    if (k < NTOK) g_best[k] = ~0ull;
    if (k < CODEBOOK) {
        float4 e = __ldg(&emb[k]);
        // e2 = ((e0*e0 + e1*e1) + e2*e2) + e3*e3, separate rn mul/add (match jnp.sum(e*e))
        float e2 = __fadd_rn(
                     __fadd_rn(
                       __fadd_rn(__fmul_rn(e.x, e.x), __fmul_rn(e.y, e.y)),
                       __fmul_rn(e.z, e.z)),
                     __fmul_rn(e.w, e.w));
        g_pkA[k] = make_ulonglong2(pack2(e.x, e.x), pack2(e.y, e.y));
        g_pkB[k] = make_ulonglong2(pack2(e.z, e.z), pack2(e.w, e.w));
        g_pkC[k] = pack2(e2, e2);
    }
}

// ---------- kernel 2: main scan ----------
// blockIdx.x : token group (512 tokens, 4/thread), blockIdx.y : codebook chunk (1024 codes)
__global__ void __launch_bounds__(TPB) vq_main(const float* __restrict__ hs,
                                               const float4* __restrict__ emb) {
    const int tid     = threadIdx.x;
    const int tokbase = blockIdx.x * (TPB * TPT);
    const int base    = blockIdx.y * CHUNK;

    // Load x for TPT tokens; slot h handles token tokbase + h*TPB + tid (lane-coalesced)
    float x[4][TPT];
    float xs[TPT];
#pragma unroll
    for (int h = 0; h < TPT; h++) {
        const int n  = tokbase + h * TPB + tid;
        const int t  = n / CH_STRIDE, hw = n % CH_STRIDE;
        const float* p = hs + t * T_STRIDE + hw;
#pragma unroll
        for (int c = 0; c < 4; c++) x[c][h] = __ldg(p + c * CH_STRIDE);
        // x2 left-assoc, separate rn ops (match jnp.sum(x*x))
        xs[h] = __fadd_rn(__fadd_rn(__fadd_rn(__fmul_rn(x[0][h], x[0][h]),
                                              __fmul_rn(x[1][h], x[1][h])),
                                    __fmul_rn(x[2][h], x[2][h])),
                          __fmul_rn(x[3][h], x[3][h]));
    }

    // Pack pairs: pair p covers halves (h=2p lo, h=2p+1 hi)
    unsigned long long X0[2], X1[2], X2[2], X3[2], XS[2];
#pragma unroll
    for (int p2 = 0; p2 < 2; p2++) {
        X0[p2] = pack2(x[0][2 * p2], x[0][2 * p2 + 1]);
        X1[p2] = pack2(x[1][2 * p2], x[1][2 * p2 + 1]);
        X2[p2] = pack2(x[2][2 * p2], x[2][2 * p2 + 1]);
        X3[p2] = pack2(x[3][2 * p2], x[3][2 * p2 + 1]);
        XS[p2] = pack2(xs[2 * p2], xs[2 * p2 + 1]);
    }
    const unsigned long long N2 = pack2(-2.0f, -2.0f);
    const float INF = __int_as_float(0x7f800000);

    float m[TPT]   = {INF, INF, INF, INF};   // running min per token
    int   gsel[TPT] = {0, 0, 0, 0};          // earliest group achieving final min

    for (int g = 0; g < NGROUP; g++) {
        float mg[TPT] = {INF, INF, INF, INF};
#pragma unroll
        for (int u = 0; u < GROUP; u++) {
            const int k = base + g * GROUP + u;
            const ulonglong2 A = g_pkA[k];
            const ulonglong2 B = g_pkB[k];
            const unsigned long long C = g_pkC[k];
#pragma unroll
            for (int p2 = 0; p2 < 2; p2++) {
                // dot = ((x0*e0 + x1*e1) + x2*e2) + x3*e3 per-half rn
                unsigned long long d = add2(mul2(X0[p2], A.x), mul2(X1[p2], A.y));
                d = add2(d, mul2(X2[p2], B.x));
                d = add2(d, mul2(X3[p2], B.y));
                const unsigned long long T = add2(XS[p2], C);   // fl(x2 + e2)
                float s0, s1;
                fma2_unpack(N2, d, T, s0, s1);  // fl(t - 2*dot), exact (2*dot exact)
                mg[2 * p2]     = fminf(mg[2 * p2], s0);
                mg[2 * p2 + 1] = fminf(mg[2 * p2 + 1], s1);
            }
        }
        // strict < : earliest group containing the eventual min wins
#pragma unroll
        for (int h = 0; h < TPT; h++)
            if (mg[h] < m[h]) { m[h] = mg[h]; gsel[h] = g; }
    }

    // Epilogue: rescan winning group scalar-ly (identical rounding) for first index
#pragma unroll
    for (int h = 0; h < TPT; h++) {
        const int kg = base + gsel[h] * GROUP;
        int idx = -1;
        for (int u = 0; u < GROUP; u++) {
            const int k = kg + u;
            const float4 e = __ldg(&emb[k]);
            const float e2 = __fadd_rn(__fadd_rn(__fadd_rn(__fmul_rn(e.x, e.x),
                                                           __fmul_rn(e.y, e.y)),
                                                 __fmul_rn(e.z, e.z)),
                                       __fmul_rn(e.w, e.w));
            const float dot = __fadd_rn(__fadd_rn(__fadd_rn(__fmul_rn(x[0][h], e.x),
                                                            __fmul_rn(x[1][h], e.y)),
                                                  __fmul_rn(x[2][h], e.z)),
                                        __fmul_rn(x[3][h], e.w));
            const float t = __fadd_rn(xs[h], e2);
            const float s = __fmaf_rn(-2.0f, dot, t);
            if (s == m[h] && idx < 0) idx = k;
        }
        if (idx < 0) idx = kg;  // safety; unreachable if rounding matches (it does)
        const int n = tokbase + h * TPB + tid;
        atomicMin(&g_best[n], make_key(m[h], idx));
    }
}

// ---------- kernel 3: extract indices (output buffer is fp32) ----------
__global__ void vq_final(float* __restrict__ out) {
    int n = blockIdx.x * blockDim.x + threadIdx.x;
    if (n < NTOK) {
        out[n] = (float)(unsigned int)(g_best[n] & 0xFFFFFFFFull);
    }
}

extern "C" void kernel_launch(void* const* d_in, const int* in_sizes, int n_in,
                              void* d_out, int out_size) {
    // Resolve input order by element count:
    //   hidden_state: 36864 elements, embedding: 131072 elements
    const float*  hs;
    const float4* emb;
    if (in_sizes[0] == NTOK * 4) {
        hs  = (const float*)d_in[0];
        emb = (const float4*)d_in[1];
    } else {
        emb = (const float4*)d_in[0];
        hs  = (const float*)d_in[1];
    }
    float* out = (float*)d_out;

    vq_prep<<<CODEBOOK / 256, 256>>>(emb);
    vq_main<<<dim3(TOKBLKS, CHUNKS, 1), TPB>>>(hs, emb);
    vq_final<<<(NTOK + 255) / 256, 256>>>(out);
}

// round 5
// speedup vs baseline: 1.4402x; 1.0615x over previous
#include <cuda_runtime.h>
#include <cstdint>

#define CODEBOOK 32768
#define NTOK     9216      // 1*4*48*48 tokens
#define CH_STRIDE 2304     // 48*48
#define T_STRIDE  9216     // 4 channels * 2304

#define TPB     128
#define TPT     4                           // tokens per thread (2 f32x2 pairs)
#define CHUNKS  32
#define CHUNK   (CODEBOOK / CHUNKS)         // 1024 codes per chunk
#define GROUP   16
#define NGROUP  (CHUNK / GROUP)             // 64 groups per chunk
#define TOKBLKS (NTOK / (TPB * TPT))        // 18 token blocks

// Scratch (static __device__ — no allocation)
__device__ ulonglong2          g_pkA[CODEBOOK];   // (e0,e0) (e1,e1) packed f32x2
__device__ ulonglong2          g_pkB[CODEBOOK];   // (e2,e2) (e3,e3)
__device__ unsigned long long  g_pkC[CODEBOOK];   // (e2sum, e2sum)
__device__ unsigned long long  g_best[NTOK];      // (ford(s) << 32) | global_group_id

// ---------- packed f32x2 helpers ----------
static __device__ __forceinline__ unsigned long long pack2(float lo, float hi) {
    unsigned long long r;
    asm("mov.b64 %0,{%1,%2};" : "=l"(r) : "f"(lo), "f"(hi));
    return r;
}
static __device__ __forceinline__ unsigned long long mul2(unsigned long long a, unsigned long long b) {
    unsigned long long d;
    asm("mul.rn.f32x2 %0,%1,%2;" : "=l"(d) : "l"(a), "l"(b));
    return d;
}
static __device__ __forceinline__ unsigned long long add2(unsigned long long a, unsigned long long b) {
    unsigned long long d;
    asm("add.rn.f32x2 %0,%1,%2;" : "=l"(d) : "l"(a), "l"(b));
    return d;
}
// s = fma(a, b, c) per half; result returned as two scalar floats (register halves)
static __device__ __forceinline__ void fma2_unpack(unsigned long long a, unsigned long long b,
                                                   unsigned long long c, float& lo, float& hi) {
    asm("{\n\t"
        ".reg .b64 t;\n\t"
        "fma.rn.f32x2 t,%2,%3,%4;\n\t"
        "mov.b64 {%0,%1},t;\n\t"
        "}" : "=f"(lo), "=f"(hi) : "l"(a), "l"(b), "l"(c));
}

// scores are positive finite; ford is monotone and invertible there
static __device__ __forceinline__ unsigned int ford(float v) {
    return __float_as_uint(v) | 0x80000000u;
}
static __device__ __forceinline__ unsigned long long make_key(float s, unsigned int grp) {
    return (((unsigned long long)ford(s)) << 32) | grp;
}

// ---------- kernel 1: codebook transform + scratch init ----------
__global__ void vq_prep(const float4* __restrict__ emb) {
    int k = blockIdx.x * blockDim.x + threadIdx.x;
    if (k < NTOK) g_best[k] = ~0ull;
    if (k < CODEBOOK) {
        float4 e = __ldg(&emb[k]);
        // e2 = ((e0*e0 + e1*e1) + e2*e2) + e3*e3, separate rn mul/add (match jnp.sum(e*e))
        float e2 = __fadd_rn(
                     __fadd_rn(
                       __fadd_rn(__fmul_rn(e.x, e.x), __fmul_rn(e.y, e.y)),
                       __fmul_rn(e.z, e.z)),
                     __fmul_rn(e.w, e.w));
        g_pkA[k] = make_ulonglong2(pack2(e.x, e.x), pack2(e.y, e.y));
        g_pkB[k] = make_ulonglong2(pack2(e.z, e.z), pack2(e.w, e.w));
        g_pkC[k] = pack2(e2, e2);
    }
}

// ---------- kernel 2: main scan (min value + first group only) ----------
// blockIdx.x : token group (512 tokens, 4/thread), blockIdx.y : codebook chunk (1024 codes)
__global__ void __launch_bounds__(TPB) vq_main(const float* __restrict__ hs) {
    const int tid     = threadIdx.x;
    const int tokbase = blockIdx.x * (TPB * TPT);
    const int base    = blockIdx.y * CHUNK;

    // Load x for TPT tokens; slot h handles token tokbase + h*TPB + tid (lane-coalesced)
    float x[4][TPT];
    float xs[TPT];
#pragma unroll
    for (int h = 0; h < TPT; h++) {
        const int n  = tokbase + h * TPB + tid;
        const int t  = n / CH_STRIDE, hw = n % CH_STRIDE;
        const float* p = hs + t * T_STRIDE + hw;
#pragma unroll
        for (int c = 0; c < 4; c++) x[c][h] = __ldg(p + c * CH_STRIDE);
        xs[h] = __fadd_rn(__fadd_rn(__fadd_rn(__fmul_rn(x[0][h], x[0][h]),
                                              __fmul_rn(x[1][h], x[1][h])),
                                    __fmul_rn(x[2][h], x[2][h])),
                          __fmul_rn(x[3][h], x[3][h]));
    }

    unsigned long long X0[2], X1[2], X2[2], X3[2], XS[2];
#pragma unroll
    for (int p2 = 0; p2 < 2; p2++) {
        X0[p2] = pack2(x[0][2 * p2], x[0][2 * p2 + 1]);
        X1[p2] = pack2(x[1][2 * p2], x[1][2 * p2 + 1]);
        X2[p2] = pack2(x[2][2 * p2], x[2][2 * p2 + 1]);
        X3[p2] = pack2(x[3][2 * p2], x[3][2 * p2 + 1]);
        XS[p2] = pack2(xs[2 * p2], xs[2 * p2 + 1]);
    }
    const unsigned long long N2 = pack2(-2.0f, -2.0f);
    const float INF = __int_as_float(0x7f800000);

    float m[TPT]    = {INF, INF, INF, INF};  // running chunk min per token
    int   gsel[TPT] = {0, 0, 0, 0};          // earliest group achieving it

    for (int g = 0; g < NGROUP; g++) {
        float mg[TPT] = {INF, INF, INF, INF};
#pragma unroll
        for (int u = 0; u < GROUP; u++) {
            const int k = base + g * GROUP + u;
            const ulonglong2 A = g_pkA[k];
            const ulonglong2 B = g_pkB[k];
            const unsigned long long C = g_pkC[k];
#pragma unroll
            for (int p2 = 0; p2 < 2; p2++) {
                // dot = ((x0*e0 + x1*e1) + x2*e2) + x3*e3 per-half rn (matches reference)
                unsigned long long d = add2(mul2(X0[p2], A.x), mul2(X1[p2], A.y));
                d = add2(d, mul2(X2[p2], B.x));
                d = add2(d, mul2(X3[p2], B.y));
                const unsigned long long T = add2(XS[p2], C);   // fl(x2 + e2)
                float s0, s1;
                fma2_unpack(N2, d, T, s0, s1);  // fl(t - 2*dot), single rounding == reference
                mg[2 * p2]     = fminf(mg[2 * p2], s0);
                mg[2 * p2 + 1] = fminf(mg[2 * p2 + 1], s1);
            }
        }
#pragma unroll
        for (int h = 0; h < TPT; h++)
            if (mg[h] < m[h]) { m[h] = mg[h]; gsel[h] = g; }   // strict <: earliest group wins
    }

#pragma unroll
    for (int h = 0; h < TPT; h++) {
        const int n = tokbase + h * TPB + tid;
        atomicMin(&g_best[n], make_key(m[h], (unsigned)(blockIdx.y * NGROUP + gsel[h])));
    }
}

// ---------- kernel 3: recover first index in winning group, write as float ----------
// Half-warp per token: 16 lanes each evaluate one code; ballot picks first exact match.
__global__ void vq_final(const float* __restrict__ hs,
                         const float4* __restrict__ emb,
                         float* __restrict__ out) {
    const int lane = threadIdx.x & 31;
    const int half = lane >> 4;                       // 0 or 1
    const int u    = lane & 15;                       // code slot within group
    const int n    = (blockIdx.x * blockDim.x + threadIdx.x) >> 4;  // token (2 per warp)
    if (n >= NTOK) return;

    const unsigned long long key = g_best[n];
    const unsigned int grp    = (unsigned int)(key & 0xFFFFFFFFull);
    const unsigned int m_bits = ((unsigned int)(key >> 32)) & 0x7FFFFFFFu;
    const int kbase = (int)grp * GROUP;

    // token features (broadcast loads across the half-warp)
    const int t = n / CH_STRIDE, hw = n % CH_STRIDE;
    const float* p = hs + t * T_STRIDE + hw;
    const float x0 = __ldg(p), x1 = __ldg(p + CH_STRIDE),
                x2 = __ldg(p + 2 * CH_STRIDE), x3 = __ldg(p + 3 * CH_STRIDE);
    const float xsv = __fadd_rn(__fadd_rn(__fadd_rn(__fmul_rn(x0, x0), __fmul_rn(x1, x1)),
                                          __fmul_rn(x2, x2)), __fmul_rn(x3, x3));

    const float4 e = __ldg(&emb[kbase + u]);
    const float e2 = __fadd_rn(__fadd_rn(__fadd_rn(__fmul_rn(e.x, e.x), __fmul_rn(e.y, e.y)),
                                         __fmul_rn(e.z, e.z)), __fmul_rn(e.w, e.w));
    const float dot = __fadd_rn(__fadd_rn(__fadd_rn(__fmul_rn(x0, e.x), __fmul_rn(x1, e.y)),
                                          __fmul_rn(x2, e.z)), __fmul_rn(x3, e.w));
    const float s = __fmaf_rn(-2.0f, dot, __fadd_rn(xsv, e2));

    const unsigned int bal = __ballot_sync(0xFFFFFFFFu, __float_as_uint(s) == m_bits);
    if (u == 0) {
        const unsigned int mybits = half ? (bal >> 16) : (bal & 0xFFFFu);
        const int first = mybits ? (__ffs(mybits) - 1) : 0;   // fallback: group base
        out[n] = (float)(kbase + first);
    }
}

extern "C" void kernel_launch(void* const* d_in, const int* in_sizes, int n_in,
                              void* d_out, int out_size) {
    // Resolve input order by element count: hidden_state 36864, embedding 131072
    const float*  hs;
    const float4* emb;
    if (in_sizes[0] == NTOK * 4) {
        hs  = (const float*)d_in[0];
        emb = (const float4*)d_in[1];
    } else {
        emb = (const float4*)d_in[0];
        hs  = (const float*)d_in[1];
    }
    float* out = (float*)d_out;

    vq_prep<<<CODEBOOK / 256, 256>>>(emb);
    vq_main<<<dim3(TOKBLKS, CHUNKS, 1), TPB>>>(hs);
    // 16 lanes per token -> NTOK*16 threads
    vq_final<<<(NTOK * 16 + 255) / 256, 256>>>(hs, emb, out);
}